// round 11
// baseline (speedup 1.0000x reference)
#include <cuda_runtime.h>
#include <cuda_fp16.h>

#define CANVAS 1024
#define NSH 64
#define TEXN 512
#define QDIM 513                 // tap-origin index range 0..512 (tex coord -1..511)
#define BW 129                   // morton blocks per row: ceil(513/4)
#define BH 257                   // morton block rows:     ceil(513/2)
#define QTE (BW * BH * 8)        // entries per table per texture
#define T_EPS 1e-4f

// Split quad storage: for tap-origin (yi, xi),
//   table A entry = { v00.rg, v00.ba, v01.rg, v01.ba }  (top row taps,    16B)
//   table B entry = { v10.rg, v10.ba, v11.rg, v11.ba }  (bottom row taps, 16B)
// Same index into both tables. 128B line = 8 origins (Morton 4 wide x 2 tall).
// Out-of-bounds taps stored as zero (matches reference zero-fill).
__device__ uint4 g_texA[4 * QTE];   // ~17 MB
__device__ uint4 g_texB[4 * QTE];   // ~17 MB

__device__ __forceinline__ int half_off(int qy, int qx) {
    return ((((qy >> 1) * BW + (qx >> 2)) << 3) | ((qy & 1) << 2) | (qx & 3));
}

// Per-shape transform/color record (compacted into smem per tile).
struct __align__(16) ShapeXfm {
    float tx, ty, m00, m01;
    float m10, m11, r, g;
    float b; int texoff; float pad0, pad1;
};

// ---------------------------------------------------------------------------
// Kernel 1: build the two fp16 half-tables (Morton 4x2 swizzled).
// ---------------------------------------------------------------------------
__global__ __launch_bounds__(256) void build_quad_kernel(const float* __restrict__ tex) {
    int t  = blockIdx.y;
    int qy = blockIdx.x;                   // 0..512
    int yi = qy - 1;                       // -1..511
    const int NPIX = TEXN * TEXN;
    const float* base = tex + (size_t)t * 4 * NPIX;
    uint4* tabA = g_texA + t * QTE;
    uint4* tabB = g_texB + t * QTE;

    for (int qx = threadIdx.x; qx < QDIM; qx += 256) {
        int xi = qx - 1;                   // -1..511

        float vals[4][4];  // [tap][chan]  taps: 00,01,10,11
        #pragma unroll
        for (int ty2 = 0; ty2 < 2; ty2++) {
            #pragma unroll
            for (int tx2 = 0; tx2 < 2; tx2++) {
                int y = yi + ty2, x = xi + tx2;
                bool ok = ((unsigned)x < (unsigned)TEXN) && ((unsigned)y < (unsigned)TEXN);
                int off = y * TEXN + x;
                #pragma unroll
                for (int ch = 0; ch < 4; ch++)
                    vals[ty2 * 2 + tx2][ch] = ok ? __ldg(base + ch * NPIX + off) : 0.0f;
            }
        }

        __half2 h[8];
        #pragma unroll
        for (int tap = 0; tap < 4; tap++) {
            h[tap * 2 + 0] = __floats2half2_rn(vals[tap][0], vals[tap][1]);
            h[tap * 2 + 1] = __floats2half2_rn(vals[tap][2], vals[tap][3]);
        }

        int o = half_off(qy, qx);
        tabA[o] = *reinterpret_cast<uint4*>(&h[0]);   // v00, v01
        tabB[o] = *reinterpret_cast<uint4*>(&h[4]);   // v10, v11
    }
}

// One bilinear sample + composite step. No-op if lane saturated or outside.
__device__ __forceinline__ void sample_composite(
    int texoff, float cr, float cg, float cb,
    float fu, float fv,
    float& Cr, float& Cg, float& Cb, float& T)
{
    if (T <= T_EPS) return;
    int xi1 = __float2int_rd(fu);
    int yi1 = __float2int_rd(fv);
    if (((unsigned)xi1 >= (unsigned)QDIM) || ((unsigned)yi1 >= (unsigned)QDIM))
        return;

    float wx = fu - (float)xi1;
    float wy = fv - (float)yi1;

    int o = texoff + half_off(yi1, xi1);
    uint4 qa = __ldg(g_texA + o);    // v00, v01
    uint4 qb = __ldg(g_texB + o);    // v10, v11

    __half2 rg00 = *reinterpret_cast<const __half2*>(&qa.x);
    __half2 ba00 = *reinterpret_cast<const __half2*>(&qa.y);
    __half2 rg01 = *reinterpret_cast<const __half2*>(&qa.z);
    __half2 ba01 = *reinterpret_cast<const __half2*>(&qa.w);
    __half2 rg10 = *reinterpret_cast<const __half2*>(&qb.x);
    __half2 ba10 = *reinterpret_cast<const __half2*>(&qb.y);
    __half2 rg11 = *reinterpret_cast<const __half2*>(&qb.z);
    __half2 ba11 = *reinterpret_cast<const __half2*>(&qb.w);

    __half2 wx2 = __float2half2_rn(wx);
    __half2 wy2 = __float2half2_rn(wy);

    __half2 rg_t = __hfma2(wx2, __hsub2(rg01, rg00), rg00);
    __half2 ba_t = __hfma2(wx2, __hsub2(ba01, ba00), ba00);
    __half2 rg_b = __hfma2(wx2, __hsub2(rg11, rg10), rg10);
    __half2 ba_b = __hfma2(wx2, __hsub2(ba11, ba10), ba10);
    __half2 rg   = __hfma2(wy2, __hsub2(rg_b, rg_t), rg_t);
    __half2 ba   = __hfma2(wy2, __hsub2(ba_b, ba_t), ba_t);

    float2 rgf = __half22float2(rg);
    float2 baf = __half22float2(ba);

    float Ta = T * baf.y;           // T * alpha
    Cr = fmaf(Ta, rgf.x * cr, Cr);
    Cg = fmaf(Ta, rgf.y * cg, Cg);
    Cb = fmaf(Ta, baf.x * cb, Cb);
    T  = T - Ta;                    // T *= (1 - a)
}

// ---------------------------------------------------------------------------
// Kernel 2: render. FOUR pixels per thread (2x2 quad); warp = 16x8 pixel
// block; block = 32x32 tile. Per-tile shape compaction + per-warp bbox cull,
// reverse compositing with transmittance early-exit, fp16 bilerp.
// ---------------------------------------------------------------------------
__global__ __launch_bounds__(256) void render_kernel(const int* __restrict__ st,
                                                     const float* __restrict__ params,
                                                     float* __restrict__ out) {
    __shared__ ShapeXfm sxf[NSH];     // compacted, order-preserving
    __shared__ float4   sbox[NSH];    // compacted bboxes (for warp-level cull)
    __shared__ int s_cnt0;
    __shared__ int s_nlive;

    int tid = threadIdx.x;            // 0..255 flat

    // tile bounds (pixel centers), tile = 32x32
    float tX0 = (float)(blockIdx.x * 32) + 0.5f;
    float tX1 = tX0 + 31.0f;
    float tY0 = (float)(blockIdx.y * 32) + 0.5f;
    float tY1 = tY0 + 31.0f;

    // --- per-tile shape prep + compaction (first 2 warps) ---
    bool pass = false;
    ShapeXfm xf;
    float4 bbox;
    if (tid < NSH) {
        const float* p = params + tid * 9;
        float tx = p[0] * (float)CANVAS;
        float ty = p[1] * (float)CANVAS;
        float W  = (float)CANVAS * (0.05f + 0.95f * p[2]);
        float H  = (float)CANVAS * (0.05f + 0.95f * p[3]);
        float as = p[4], ac = p[5];
        float nrm = sqrtf(as * as + ac * ac) + 1e-8f;
        float c = ac / nrm, s = as / nrm;
        float fx = (float)TEXN / W;
        float fy = (float)TEXN / H;

        xf.tx = tx; xf.ty = ty;
        xf.m00 =  c * fx;  xf.m01 = s * fx;
        xf.m10 = -s * fy;  xf.m11 = c * fy;
        xf.r = p[6]; xf.g = p[7]; xf.b = p[8];
        xf.texoff = st[tid] * QTE;
        xf.pad0 = xf.pad1 = 0.f;

        float uh = 0.5f * W * (1.0f + 2.0f / TEXN) + 2.0f;
        float vh = 0.5f * H * (1.0f + 2.0f / TEXN) + 2.0f;
        float ex = fabsf(c) * uh + fabsf(s) * vh;
        float ey = fabsf(s) * uh + fabsf(c) * vh;
        bbox = make_float4(tx - ex, tx + ex, ty - ey, ty + ey);
        pass = !(tX1 < bbox.x || tX0 > bbox.y || tY1 < bbox.z || tY0 > bbox.w);
    }

    unsigned mask = 0;
    int pos = 0;
    if (tid < NSH) {
        mask = __ballot_sync(0xffffffffu, pass);
        pos = __popc(mask & ((1u << (tid & 31)) - 1u));
        if (tid == 0) s_cnt0 = __popc(mask);
    }
    __syncthreads();
    if (tid < NSH) {
        int base = (tid < 32) ? 0 : s_cnt0;
        if (pass) { sxf[base + pos] = xf; sbox[base + pos] = bbox; }
        if (tid == 32) s_nlive = s_cnt0 + __popc(mask);
    }
    __syncthreads();

    int nlive = s_nlive;

    // warp -> 16x8 pixel block; thread -> 2x2 pixel quad
    int lane = tid & 31;
    int warp = tid >> 5;              // 0..7
    int bx0 = blockIdx.x * 32 + (warp & 1) * 16;
    int by0 = blockIdx.y * 32 + (warp >> 1) * 8;
    int x0 = bx0 + (lane & 7) * 2;
    int y0 = by0 + (lane >> 3) * 2;
    float px = (float)x0 + 0.5f;
    float py = (float)y0 + 0.5f;

    // warp block bounds (pixel centers) — warp-uniform 16x8
    float wX0 = (float)bx0 + 0.5f, wX1 = wX0 + 15.0f;
    float wY0 = (float)by0 + 0.5f, wY1 = wY0 + 7.0f;

    // Reverse compositing per pixel: out = C + T * canvas0(=1)
    // indices: 0=(x,y) 1=(x+1,y) 2=(x,y+1) 3=(x+1,y+1)
    float Cr0=0.f,Cg0=0.f,Cb0=0.f,T0=1.f;
    float Cr1=0.f,Cg1=0.f,Cb1=0.f,T1=1.f;
    float Cr2=0.f,Cg2=0.f,Cb2=0.f,T2=1.f;
    float Cr3=0.f,Cg3=0.f,Cb3=0.f,T3=1.f;

    for (int k = nlive - 1; k >= 0; k--) {
        bool sat = (T0 <= T_EPS) && (T1 <= T_EPS) && (T2 <= T_EPS) && (T3 <= T_EPS);
        if (__all_sync(0xffffffffu, sat)) break;

        // warp-uniform 16x8 bbox cull
        float4 bb = sbox[k];
        if (wX1 < bb.x || wX0 > bb.y || wY1 < bb.z || wY0 > bb.w)
            continue;

        const ShapeXfm rec = sxf[k];
        float dx = px - rec.tx;
        float dy = py - rec.ty;
        float fu0 = fmaf(rec.m00, dx, fmaf(rec.m01, dy, 256.5f));
        float fv0 = fmaf(rec.m10, dx, fmaf(rec.m11, dy, 256.5f));
        float fu1 = fu0 + rec.m00;             // x+1
        float fv1 = fv0 + rec.m10;
        float fu2 = fu0 + rec.m01;             // y+1
        float fv2 = fv0 + rec.m11;
        float fu3 = fu1 + rec.m01;             // x+1, y+1
        float fv3 = fv1 + rec.m11;

        sample_composite(rec.texoff, rec.r, rec.g, rec.b, fu0, fv0, Cr0, Cg0, Cb0, T0);
        sample_composite(rec.texoff, rec.r, rec.g, rec.b, fu1, fv1, Cr1, Cg1, Cb1, T1);
        sample_composite(rec.texoff, rec.r, rec.g, rec.b, fu2, fv2, Cr2, Cg2, Cb2, T2);
        sample_composite(rec.texoff, rec.r, rec.g, rec.b, fu3, fv3, Cr3, Cg3, Cb3, T3);
    }

    // x-pair stores as float2 (x0 even -> 8B aligned)
    int o0 = y0 * CANVAS + x0;
    int o1 = o0 + CANVAS;
    const int P = CANVAS * CANVAS;
    *reinterpret_cast<float2*>(out + o0)         = make_float2(Cr0 + T0, Cr1 + T1);
    *reinterpret_cast<float2*>(out + o0 + P)     = make_float2(Cg0 + T0, Cg1 + T1);
    *reinterpret_cast<float2*>(out + o0 + 2 * P) = make_float2(Cb0 + T0, Cb1 + T1);
    *reinterpret_cast<float2*>(out + o1)         = make_float2(Cr2 + T2, Cr3 + T3);
    *reinterpret_cast<float2*>(out + o1 + P)     = make_float2(Cg2 + T2, Cg3 + T3);
    *reinterpret_cast<float2*>(out + o1 + 2 * P) = make_float2(Cb2 + T2, Cb3 + T3);
}

// ---------------------------------------------------------------------------
extern "C" void kernel_launch(void* const* d_in, const int* in_sizes, int n_in,
                              void* d_out, int out_size) {
    const int*   shape_type = (const int*)d_in[0];
    const float* params     = (const float*)d_in[1];
    const float* textures   = (const float*)d_in[2];
    float* out = (float*)d_out;

    dim3 bgrid(QDIM, 4);
    build_quad_kernel<<<bgrid, 256>>>(textures);

    dim3 blk(256);
    dim3 grd(CANVAS / 32, CANVAS / 32);
    render_kernel<<<grd, blk>>>(shape_type, params, out);
}